// round 1
// baseline (speedup 1.0000x reference)
#include <cuda_runtime.h>

// EnhancedLDEPooling: B=16, T=2048, D=256, K=8
// Kernel 1: fused distances + softmax + weighted accumulation (single pass over x).
// Kernel 2: reduce chunk partials, form mean/var, layernorm(512), write output.

#define BB 16
#define TT 2048
#define DD 256
#define KK 8
#define ROWS 128              // rows of T per block
#define CH (TT / ROWS)        // 16 chunks per batch
#define LOG2E 1.4426950408889634f

// deterministic scratch (no atomics): per (b, chunk) partials
__device__ float g_wx [BB * CH * KK * DD];   // sum w * x
__device__ float g_wx2[BB * CH * KK * DD];   // sum w * x^2
__device__ float g_sw [BB * CH * KK];        // sum w

// ---- f32x2 packed math (Blackwell sm_103a) ----
static __device__ __forceinline__ unsigned long long pk2(float lo, float hi) {
    unsigned long long r;
    asm("mov.b64 %0, {%1, %2};" : "=l"(r) : "f"(lo), "f"(hi));
    return r;
}
static __device__ __forceinline__ void upk2(unsigned long long v, float& a, float& b) {
    asm("mov.b64 {%0, %1}, %2;" : "=f"(a), "=f"(b) : "l"(v));
}
static __device__ __forceinline__ unsigned long long ffma2(unsigned long long a,
                                                           unsigned long long b,
                                                           unsigned long long c) {
    unsigned long long d;
    asm("fma.rn.f32x2 %0, %1, %2, %3;" : "=l"(d) : "l"(a), "l"(b), "l"(c));
    return d;
}
static __device__ __forceinline__ unsigned long long fmul2(unsigned long long a,
                                                           unsigned long long b) {
    unsigned long long d;
    asm("mul.rn.f32x2 %0, %1, %2;" : "=l"(d) : "l"(a), "l"(b));
    return d;
}
static __device__ __forceinline__ float ex2_fast(float v) {
    float r;
    asm("ex2.approx.f32 %0, %1;" : "=f"(r) : "f"(v));
    return r;
}

__global__ __launch_bounds__(128, 2)
void lde_main(const float* __restrict__ x,
              const float* __restrict__ centers,
              const float* __restrict__ scale,
              const float* __restrict__ temperature)
{
    const int tid  = threadIdx.x;
    const int warp = tid >> 5;
    const int lane = tid & 31;
    const int b    = blockIdx.x >> 4;
    const int ch   = blockIdx.x & 15;

    __shared__ float sWX [KK][DD];
    __shared__ float sWX2[KK][DD];
    __shared__ float sSW [KK];

    // centers into packed registers: lane owns d = lane*4..+3 and 128+lane*4..+3
    unsigned long long cc[KK][4];
    const float4* c4 = (const float4*)centers;
#pragma unroll
    for (int k = 0; k < KK; k++) {
        float4 a = __ldg(c4 + k * (DD / 4) + lane);
        float4 q = __ldg(c4 + k * (DD / 4) + 32 + lane);
        cc[k][0] = pk2(a.x, a.y); cc[k][1] = pk2(a.z, a.w);
        cc[k][2] = pk2(q.x, q.y); cc[k][3] = pk2(q.z, q.w);
    }

    // ||c_k||^2 (warp-reduced, all lanes get it)
    float c2[KK];
#pragma unroll
    for (int k = 0; k < KK; k++) {
        unsigned long long s = ffma2(cc[k][0], cc[k][0],
                               ffma2(cc[k][1], cc[k][1],
                               ffma2(cc[k][2], cc[k][2],
                               fmul2(cc[k][3], cc[k][3]))));
        float u, v; upk2(s, u, v);
        c2[k] = u + v;
    }
#pragma unroll
    for (int off = 16; off; off >>= 1) {
#pragma unroll
        for (int k = 0; k < KK; k++)
            c2[k] += __shfl_xor_sync(0xffffffffu, c2[k], off);
    }

    const float tmp = __ldg(temperature);
    float a2[KK], e2[KK];
#pragma unroll
    for (int k = 0; k < KK; k++) {
        a2[k] = tmp * __ldg(scale + k) * LOG2E;   // base-2 logit scale
        e2[k] = a2[k] * c2[k];
    }

    // accumulators: packed (k, d-pair)
    unsigned long long aw[KK][4], aw2[KK][4];
    float asw[KK];
#pragma unroll
    for (int k = 0; k < KK; k++) {
        asw[k] = 0.f;
#pragma unroll
        for (int p = 0; p < 4; p++) { aw[k][p] = 0ull; aw2[k][p] = 0ull; }
    }

    const int row0 = ch * ROWS + warp * (ROWS / 4);
    const float4* xb = (const float4*)(x + (size_t)b * TT * DD);

    // manual prefetch of first row
    float4 na = __ldg(xb + (size_t)row0 * (DD / 4) + lane);
    float4 nb = __ldg(xb + (size_t)row0 * (DD / 4) + 32 + lane);

#pragma unroll 1
    for (int i = 0; i < ROWS / 4; i++) {
        float4 xa = na, xq = nb;
        if (i + 1 < ROWS / 4) {
            const float4* nx = xb + (size_t)(row0 + i + 1) * (DD / 4);
            na = __ldg(nx + lane);
            nb = __ldg(nx + 32 + lane);
        }
        unsigned long long xp0 = pk2(xa.x, xa.y), xp1 = pk2(xa.z, xa.w);
        unsigned long long xp2 = pk2(xq.x, xq.y), xp3 = pk2(xq.z, xq.w);

        // ||x||^2 partial
        unsigned long long s2 = ffma2(xp0, xp0, ffma2(xp1, xp1,
                               ffma2(xp2, xp2, fmul2(xp3, xp3))));
        float t0, t1; upk2(s2, t0, t1);
        float x2 = t0 + t1;

        // dot(x, c_k) partials
        float dot[KK];
#pragma unroll
        for (int k = 0; k < KK; k++) {
            unsigned long long s = ffma2(xp0, cc[k][0],
                                   ffma2(xp1, cc[k][1],
                                   ffma2(xp2, cc[k][2],
                                   fmul2(xp3, cc[k][3]))));
            float u, v; upk2(s, u, v);
            dot[k] = u + v;
        }

        // warp butterfly reduce 9 values
#pragma unroll
        for (int off = 16; off; off >>= 1) {
            x2 += __shfl_xor_sync(0xffffffffu, x2, off);
#pragma unroll
            for (int k = 0; k < KK; k++)
                dot[k] += __shfl_xor_sync(0xffffffffu, dot[k], off);
        }

        // softmax over k (base-2): logit2 = a2_k*(2*dot - x2) - a2_k*c2_k
        float w[KK];
#pragma unroll
        for (int k = 0; k < KK; k++) {
            float u = fmaf(2.f, dot[k], -x2);
            w[k] = fmaf(a2[k], u, -e2[k]);
        }
        float m = w[0];
#pragma unroll
        for (int k = 1; k < KK; k++) m = fmaxf(m, w[k]);
        float S = 0.f;
#pragma unroll
        for (int k = 0; k < KK; k++) { w[k] = ex2_fast(w[k] - m); S += w[k]; }
        const float inv = __fdividef(1.f, S);
#pragma unroll
        for (int k = 0; k < KK; k++) { w[k] *= inv; asw[k] += w[k]; }

        // accumulate w*x, w*x^2 (packed)
        unsigned long long xx0 = fmul2(xp0, xp0), xx1 = fmul2(xp1, xp1);
        unsigned long long xx2 = fmul2(xp2, xp2), xx3 = fmul2(xp3, xp3);
#pragma unroll
        for (int k = 0; k < KK; k++) {
            unsigned long long wp = pk2(w[k], w[k]);
            aw [k][0] = ffma2(wp, xp0, aw [k][0]);
            aw [k][1] = ffma2(wp, xp1, aw [k][1]);
            aw [k][2] = ffma2(wp, xp2, aw [k][2]);
            aw [k][3] = ffma2(wp, xp3, aw [k][3]);
            aw2[k][0] = ffma2(wp, xx0, aw2[k][0]);
            aw2[k][1] = ffma2(wp, xx1, aw2[k][1]);
            aw2[k][2] = ffma2(wp, xx2, aw2[k][2]);
            aw2[k][3] = ffma2(wp, xx3, aw2[k][3]);
        }
    }

    // cross-warp reduction into shared (serialized over 4 warps, no atomics)
    for (int wv = 0; wv < 4; wv++) {
        if (warp == wv) {
#pragma unroll
            for (int k = 0; k < KK; k++) {
#pragma unroll
                for (int h = 0; h < 2; h++) {
                    float p0, p1, p2, p3;
                    upk2(aw[k][2 * h], p0, p1);
                    upk2(aw[k][2 * h + 1], p2, p3);
                    float* dst = &sWX[k][h * 128 + lane * 4];
                    if (wv == 0) { dst[0] = p0; dst[1] = p1; dst[2] = p2; dst[3] = p3; }
                    else         { dst[0] += p0; dst[1] += p1; dst[2] += p2; dst[3] += p3; }
                    upk2(aw2[k][2 * h], p0, p1);
                    upk2(aw2[k][2 * h + 1], p2, p3);
                    float* dst2 = &sWX2[k][h * 128 + lane * 4];
                    if (wv == 0) { dst2[0] = p0; dst2[1] = p1; dst2[2] = p2; dst2[3] = p3; }
                    else         { dst2[0] += p0; dst2[1] += p1; dst2[2] += p2; dst2[3] += p3; }
                }
            }
            if (lane == 0) {
#pragma unroll
                for (int k = 0; k < KK; k++) {
                    if (wv == 0) sSW[k] = asw[k];
                    else         sSW[k] += asw[k];
                }
            }
        }
        __syncthreads();
    }

    // write block partials to global scratch (coalesced)
    const int cbase = (b * CH + ch) * KK;
    float4* gw  = (float4*)g_wx;
    float4* gw2 = (float4*)g_wx2;
    for (int idx = tid; idx < KK * DD / 4; idx += 128) {
        int k = idx >> 6;
        int q = idx & 63;
        *(gw  + (size_t)(cbase + k) * (DD / 4) + q) = *(const float4*)&sWX [k][q * 4];
        *(gw2 + (size_t)(cbase + k) * (DD / 4) + q) = *(const float4*)&sWX2[k][q * 4];
    }
    if (tid < KK) g_sw[cbase + tid] = sSW[tid];
}

__global__ __launch_bounds__(256)
void lde_finalize(const float* __restrict__ centers, float* __restrict__ out)
{
    const int b = blockIdx.x >> 3;
    const int k = blockIdx.x & 7;
    const int d = threadIdx.x;   // 0..255

    float sw = 0.f;
#pragma unroll
    for (int c = 0; c < CH; c++) sw += g_sw[(b * CH + c) * KK + k];

    float swx = 0.f, swx2 = 0.f;
#pragma unroll
    for (int c = 0; c < CH; c++) {
        size_t base = ((size_t)(b * CH + c) * KK + k) * DD + d;
        swx  += g_wx [base];
        swx2 += g_wx2[base];
    }

    const float cv   = __ldg(centers + k * DD + d);
    const float mean = fmaf(-cv, sw, swx);
    const float E    = fmaf(cv * cv, sw, fmaf(-2.f * cv, swx, swx2));
    const float var  = fmaf(-mean, mean, E);

    // layernorm over 512 = [mean_0..255 | var_0..255], two-pass
    __shared__ float red[8];
    float s = mean + var;
#pragma unroll
    for (int off = 16; off; off >>= 1) s += __shfl_xor_sync(0xffffffffu, s, off);
    if ((d & 31) == 0) red[d >> 5] = s;
    __syncthreads();
    float tot = 0.f;
#pragma unroll
    for (int i = 0; i < 8; i++) tot += red[i];
    const float mu = tot * (1.f / 512.f);
    __syncthreads();

    const float dm = mean - mu, dv = var - mu;
    float sq = dm * dm + dv * dv;
#pragma unroll
    for (int off = 16; off; off >>= 1) sq += __shfl_xor_sync(0xffffffffu, sq, off);
    if ((d & 31) == 0) red[d >> 5] = sq;
    __syncthreads();
    float tot2 = 0.f;
#pragma unroll
    for (int i = 0; i < 8; i++) tot2 += red[i];
    const float rstd = rsqrtf(tot2 * (1.f / 512.f) + 1e-5f);

    float* o = out + (size_t)b * (KK * 2 * DD) + k * (2 * DD);
    o[d]      = dm * rstd;
    o[DD + d] = dv * rstd;
}

extern "C" void kernel_launch(void* const* d_in, const int* in_sizes, int n_in,
                              void* d_out, int out_size)
{
    // match inputs by element count (robust to metadata ordering)
    const float* x = nullptr; const float* centers = nullptr;
    const float* scale = nullptr; const float* temperature = nullptr;
    for (int i = 0; i < n_in; i++) {
        switch (in_sizes[i]) {
            case BB * TT * DD: x = (const float*)d_in[i]; break;
            case KK * DD:      centers = (const float*)d_in[i]; break;
            case KK:           scale = (const float*)d_in[i]; break;
            case 1:            temperature = (const float*)d_in[i]; break;
        }
    }
    lde_main<<<BB * CH, 128>>>(x, centers, scale, temperature);
    lde_finalize<<<BB * KK, 256>>>(centers, (float*)d_out);
}

// round 2
// speedup vs baseline: 1.2031x; 1.2031x over previous
#include <cuda_runtime.h>

// EnhancedLDEPooling: B=16, T=2048, D=256, K=8
// K1: fused distance + softmax + weighted accumulation, single pass over x.
//     Warp-per-row, lane owns 8 dims as 4 f32x2 pairs. Reduce-scatter softmax.
// K2: chunk-parallel reduce of partials + mean/var + layernorm(512).

#define BB 16
#define TT 2048
#define DD 256
#define KK 8
#define ROWS 128
#define CH (TT / ROWS)
#define LOG2E 1.4426950408889634f
#define KREG 6                 // centers kept in registers; KK-KREG from smem

__device__ float g_wx [BB * CH * KK * DD];
__device__ float g_wx2[BB * CH * KK * DD];
__device__ float g_sw [BB * CH * KK];

// ---- f32x2 packed math (sm_103a) ----
static __device__ __forceinline__ unsigned long long pk2(float lo, float hi) {
    unsigned long long r;
    asm("mov.b64 %0, {%1, %2};" : "=l"(r) : "f"(lo), "f"(hi));
    return r;
}
static __device__ __forceinline__ void upk2(unsigned long long v, float& a, float& b) {
    asm("mov.b64 {%0, %1}, %2;" : "=f"(a), "=f"(b) : "l"(v));
}
static __device__ __forceinline__ unsigned long long ffma2(unsigned long long a,
                                                           unsigned long long b,
                                                           unsigned long long c) {
    unsigned long long d;
    asm("fma.rn.f32x2 %0, %1, %2, %3;" : "=l"(d) : "l"(a), "l"(b), "l"(c));
    return d;
}
static __device__ __forceinline__ unsigned long long fmul2(unsigned long long a,
                                                           unsigned long long b) {
    unsigned long long d;
    asm("mul.rn.f32x2 %0, %1, %2;" : "=l"(d) : "l"(a), "l"(b));
    return d;
}
static __device__ __forceinline__ float ex2_fast(float v) {
    float r;
    asm("ex2.approx.f32 %0, %1;" : "=f"(r) : "f"(v));
    return r;
}

// 8-value reduce-scatter across 32 lanes. After this, every lane holds the
// full warp sum of r[K_id], where K_id = 4*bit4(lane) + 2*bit3(lane) + bit2(lane).
static __device__ __forceinline__ float rscat8(float r[8], bool b4, bool b8, bool b2) {
    // stage o=16: 8 -> 4
#pragma unroll
    for (int i = 0; i < 4; i++) {
        float sel = b4 ? r[i] : r[i + 4];
        float got = __shfl_xor_sync(0xffffffffu, sel, 16);
        r[i] = (b4 ? r[i + 4] : r[i]) + got;
    }
    // stage o=8: 4 -> 2
#pragma unroll
    for (int i = 0; i < 2; i++) {
        float sel = b8 ? r[i] : r[i + 2];
        float got = __shfl_xor_sync(0xffffffffu, sel, 8);
        r[i] = (b8 ? r[i + 2] : r[i]) + got;
    }
    // stage o=4: 2 -> 1
    {
        float sel = b2 ? r[0] : r[1];
        float got = __shfl_xor_sync(0xffffffffu, sel, 4);
        r[0] = (b2 ? r[1] : r[0]) + got;
    }
    // finish over lane bits 0,1
    r[0] += __shfl_xor_sync(0xffffffffu, r[0], 2);
    r[0] += __shfl_xor_sync(0xffffffffu, r[0], 1);
    return r[0];
}

__global__ __launch_bounds__(128, 2)
void lde_main(const float* __restrict__ x,
              const float* __restrict__ centers,
              const float* __restrict__ scale,
              const float* __restrict__ temperature)
{
    const int tid  = threadIdx.x;
    const int warp = tid >> 5;
    const int lane = tid & 31;
    const int b    = blockIdx.x >> 4;
    const int ch   = blockIdx.x & 15;

    const bool b4 = (lane & 16) != 0;
    const bool b8 = (lane & 8) != 0;
    const bool b2 = (lane & 4) != 0;
    const int K_id = (b4 ? 4 : 0) + (b8 ? 2 : 0) + (b2 ? 1 : 0);

    __shared__ float sC  [KK - KREG][DD];
    __shared__ float sWX [KK][DD];
    __shared__ float sWX2[KK][DD];
    __shared__ float sSW [KK];

    // ---- prologue: centers ----
    unsigned long long cc[KREG][4];
    float c2p[KK];
    const float4* c4 = (const float4*)centers;
#pragma unroll
    for (int k = 0; k < KK; k++) {
        float4 a = __ldg(c4 + k * (DD / 4) + lane);
        float4 q = __ldg(c4 + k * (DD / 4) + 32 + lane);
        unsigned long long p0 = pk2(a.x, a.y), p1 = pk2(a.z, a.w);
        unsigned long long p2 = pk2(q.x, q.y), p3 = pk2(q.z, q.w);
        if (k < KREG) {
            cc[k][0] = p0; cc[k][1] = p1; cc[k][2] = p2; cc[k][3] = p3;
        } else if (warp == 0) {
            *(float4*)&sC[k - KREG][lane * 4]       = a;
            *(float4*)&sC[k - KREG][128 + lane * 4] = q;
        }
        unsigned long long s = ffma2(p0, p0, ffma2(p1, p1, ffma2(p2, p2, fmul2(p3, p3))));
        float u, v; upk2(s, u, v);
        c2p[k] = u + v;
    }
    const float c2L = rscat8(c2p, b4, b8, b2);   // ||c_{K_id}||^2

    const float tmp  = __ldg(temperature);
    const float a2L  = tmp * __ldg(scale + K_id) * LOG2E;
    const float ne2L = -a2L * c2L;
    __syncthreads();

    // accumulators
    unsigned long long aw[KK][4], aw2[KK][4];
    float asw = 0.f;
#pragma unroll
    for (int k = 0; k < KK; k++)
#pragma unroll
        for (int p = 0; p < 4; p++) { aw[k][p] = 0ull; aw2[k][p] = 0ull; }

    const int row0 = ch * ROWS + warp * (ROWS / 4);
    const float4* xb = (const float4*)(x + (size_t)b * TT * DD);

    float4 na = __ldg(xb + (size_t)row0 * (DD / 4) + lane);
    float4 nb = __ldg(xb + (size_t)row0 * (DD / 4) + 32 + lane);

#pragma unroll 1
    for (int i = 0; i < ROWS / 4; i++) {
        float4 xa = na, xq = nb;
        if (i + 1 < ROWS / 4) {
            const float4* nx = xb + (size_t)(row0 + i + 1) * (DD / 4);
            na = __ldg(nx + lane);
            nb = __ldg(nx + 32 + lane);
        }
        unsigned long long xp0 = pk2(xa.x, xa.y), xp1 = pk2(xa.z, xa.w);
        unsigned long long xp2 = pk2(xq.x, xq.y), xp3 = pk2(xq.z, xq.w);

        // ||x||^2 partial
        unsigned long long s2 = ffma2(xp0, xp0, ffma2(xp1, xp1,
                               ffma2(xp2, xp2, fmul2(xp3, xp3))));
        float t0, t1; upk2(s2, t0, t1);
        const float x2 = t0 + t1;

        // r_k partial = 2*dot_k - x2
        float r[KK];
#pragma unroll
        for (int k = 0; k < KREG; k++) {
            unsigned long long s = ffma2(xp0, cc[k][0],
                                   ffma2(xp1, cc[k][1],
                                   ffma2(xp2, cc[k][2],
                                   fmul2(xp3, cc[k][3]))));
            float u, v; upk2(s, u, v);
            r[k] = fmaf(2.f, u + v, -x2);
        }
#pragma unroll
        for (int k = KREG; k < KK; k++) {
            const float4* sc = (const float4*)sC[k - KREG];
            float4 a = sc[lane];
            float4 q = sc[32 + lane];
            unsigned long long p0 = pk2(a.x, a.y), p1 = pk2(a.z, a.w);
            unsigned long long p2 = pk2(q.x, q.y), p3 = pk2(q.z, q.w);
            unsigned long long s = ffma2(xp0, p0, ffma2(xp1, p1,
                                   ffma2(xp2, p2, fmul2(xp3, p3))));
            float u, v; upk2(s, u, v);
            r[k] = fmaf(2.f, u + v, -x2);
        }

        // reduce-scatter: lane gets full (2*dot - x2) for its K_id
        const float rv = rscat8(r, b4, b8, b2);
        const float logit = fmaf(a2L, rv, ne2L);

        // softmax over k (k distributed over lane bits 2,3,4)
        float m = logit;
        m = fmaxf(m, __shfl_xor_sync(0xffffffffu, m, 4));
        m = fmaxf(m, __shfl_xor_sync(0xffffffffu, m, 8));
        m = fmaxf(m, __shfl_xor_sync(0xffffffffu, m, 16));
        const float e = ex2_fast(logit - m);
        float S = e;
        S += __shfl_xor_sync(0xffffffffu, S, 4);
        S += __shfl_xor_sync(0xffffffffu, S, 8);
        S += __shfl_xor_sync(0xffffffffu, S, 16);
        const float w = e * __fdividef(1.f, S);
        asw += w;

        // all-gather the 8 weights (k lives at lane 4*k)
        float wk[KK];
#pragma unroll
        for (int k = 0; k < KK; k++)
            wk[k] = __shfl_sync(0xffffffffu, w, k * 4);

        // accumulate w*x, w*x^2 (packed)
        unsigned long long xx0 = fmul2(xp0, xp0), xx1 = fmul2(xp1, xp1);
        unsigned long long xx2 = fmul2(xp2, xp2), xx3 = fmul2(xp3, xp3);
#pragma unroll
        for (int k = 0; k < KK; k++) {
            unsigned long long wp = pk2(wk[k], wk[k]);
            aw [k][0] = ffma2(wp, xp0, aw [k][0]);
            aw [k][1] = ffma2(wp, xp1, aw [k][1]);
            aw [k][2] = ffma2(wp, xp2, aw [k][2]);
            aw [k][3] = ffma2(wp, xp3, aw [k][3]);
            aw2[k][0] = ffma2(wp, xx0, aw2[k][0]);
            aw2[k][1] = ffma2(wp, xx1, aw2[k][1]);
            aw2[k][2] = ffma2(wp, xx2, aw2[k][2]);
            aw2[k][3] = ffma2(wp, xx3, aw2[k][3]);
        }
    }

    // cross-warp merge (serialized, no atomics)
    for (int wv = 0; wv < 4; wv++) {
        if (warp == wv) {
#pragma unroll
            for (int k = 0; k < KK; k++) {
#pragma unroll
                for (int h = 0; h < 2; h++) {
                    float p0, p1, p2, p3;
                    upk2(aw[k][2 * h], p0, p1);
                    upk2(aw[k][2 * h + 1], p2, p3);
                    float* dst = &sWX[k][h * 128 + lane * 4];
                    if (wv == 0) { dst[0] = p0; dst[1] = p1; dst[2] = p2; dst[3] = p3; }
                    else         { dst[0] += p0; dst[1] += p1; dst[2] += p2; dst[3] += p3; }
                    upk2(aw2[k][2 * h], p0, p1);
                    upk2(aw2[k][2 * h + 1], p2, p3);
                    float* dst2 = &sWX2[k][h * 128 + lane * 4];
                    if (wv == 0) { dst2[0] = p0; dst2[1] = p1; dst2[2] = p2; dst2[3] = p3; }
                    else         { dst2[0] += p0; dst2[1] += p1; dst2[2] += p2; dst2[3] += p3; }
                }
            }
            if ((lane & 3) == 0) {
                int k = lane >> 2;
                if (wv == 0) sSW[k] = asw;
                else         sSW[k] += asw;
            }
        }
        __syncthreads();
    }

    // write partials (coalesced)
    const int cbase = (b * CH + ch) * KK;
    float4* gw  = (float4*)g_wx;
    float4* gw2 = (float4*)g_wx2;
    for (int idx = tid; idx < KK * DD / 4; idx += 128) {
        int k = idx >> 6;
        int q = idx & 63;
        *(gw  + (size_t)(cbase + k) * (DD / 4) + q) = *(const float4*)&sWX [k][q * 4];
        *(gw2 + (size_t)(cbase + k) * (DD / 4) + q) = *(const float4*)&sWX2[k][q * 4];
    }
    if (tid < KK) g_sw[cbase + tid] = sSW[tid];
}

// ---- K2: chunk-parallel reduce + mean/var + LN(512) ----
__global__ __launch_bounds__(512)
void lde_finalize(const float* __restrict__ centers, float* __restrict__ out)
{
    const int b = blockIdx.x >> 3;
    const int k = blockIdx.x & 7;
    const int tid = threadIdx.x;

    __shared__ float sWXc [CH][DD];   // 16 KB
    __shared__ float sWX2c[CH][DD];   // 16 KB
    __shared__ float sSum[2][DD];
    __shared__ float sStat[2 * DD];
    __shared__ float s16[CH];
    __shared__ float sSwTot;
    __shared__ float red[16];

    // parallel load of all chunk partials: 4x LDG.128 per thread
    {
        const int c = tid >> 5;        // chunk 0..15
        const int s = tid & 31;
        const size_t base = ((size_t)(b * CH + c) * KK + k) * (DD / 4);
        const float4* gw  = (const float4*)g_wx;
        const float4* gw2 = (const float4*)g_wx2;
#pragma unroll
        for (int j = 0; j < 2; j++) {
            int q = s + 32 * j;
            *(float4*)&sWXc [c][q * 4] = __ldg(gw  + base + q);
            *(float4*)&sWX2c[c][q * 4] = __ldg(gw2 + base + q);
        }
        if (tid < CH) s16[tid] = g_sw[(b * CH + tid) * KK + k];
    }
    __syncthreads();

    // chunk-sum: half 0 sums wx, half 1 sums wx2
    {
        const int half = tid >> 8;
        const int d = tid & 255;
        float s = 0.f;
        if (half == 0) {
#pragma unroll
            for (int c = 0; c < CH; c++) s += sWXc[c][d];
        } else {
#pragma unroll
            for (int c = 0; c < CH; c++) s += sWX2c[c][d];
        }
        sSum[half][d] = s;
        if (tid == 0) {
            float t = 0.f;
#pragma unroll
            for (int c = 0; c < CH; c++) t += s16[c];
            sSwTot = t;
        }
    }
    __syncthreads();

    // mean / var per d (threads 0..255)
    if (tid < DD) {
        const float sw   = sSwTot;
        const float swx  = sSum[0][tid];
        const float swx2 = sSum[1][tid];
        const float cv   = __ldg(centers + k * DD + tid);
        const float mean = fmaf(-cv, sw, swx);
        const float E    = fmaf(cv * cv, sw, fmaf(-2.f * cv, swx, swx2));
        const float var  = fmaf(-mean, mean, E);
        sStat[tid]      = mean;
        sStat[DD + tid] = var;
    }
    __syncthreads();

    // LN over 512 with 512 threads
    const float v0 = sStat[tid];
    float s = v0;
#pragma unroll
    for (int off = 16; off; off >>= 1) s += __shfl_xor_sync(0xffffffffu, s, off);
    if ((tid & 31) == 0) red[tid >> 5] = s;
    __syncthreads();
    float tot = 0.f;
#pragma unroll
    for (int i = 0; i < 16; i++) tot += red[i];
    const float mu = tot * (1.f / 512.f);
    __syncthreads();

    const float dm = v0 - mu;
    float sq = dm * dm;
#pragma unroll
    for (int off = 16; off; off >>= 1) sq += __shfl_xor_sync(0xffffffffu, sq, off);
    if ((tid & 31) == 0) red[tid >> 5] = sq;
    __syncthreads();
    float tot2 = 0.f;
#pragma unroll
    for (int i = 0; i < 16; i++) tot2 += red[i];
    const float rstd = rsqrtf(tot2 * (1.f / 512.f) + 1e-5f);

    out[(size_t)b * (KK * 2 * DD) + k * (2 * DD) + tid] = dm * rstd;
}

extern "C" void kernel_launch(void* const* d_in, const int* in_sizes, int n_in,
                              void* d_out, int out_size)
{
    const float* x = nullptr; const float* centers = nullptr;
    const float* scale = nullptr; const float* temperature = nullptr;
    for (int i = 0; i < n_in; i++) {
        switch (in_sizes[i]) {
            case BB * TT * DD: x = (const float*)d_in[i]; break;
            case KK * DD:      centers = (const float*)d_in[i]; break;
            case KK:           scale = (const float*)d_in[i]; break;
            case 1:            temperature = (const float*)d_in[i]; break;
        }
    }
    lde_main<<<BB * CH, 128>>>(x, centers, scale, temperature);
    lde_finalize<<<BB * KK, 512>>>(centers, (float*)d_out);
}

// round 4
// speedup vs baseline: 1.3528x; 1.1245x over previous
#include <cuda_runtime.h>

// EnhancedLDEPooling: B=16, T=2048, D=256, K=8
// K1: fused distance + softmax + weighted accumulation, single pass over x.
//     Warp-per-row, 2-stage software pipeline: softmax/accum of row i overlaps
//     dots/reduce-scatter of row i+1.
// K2: chunk-parallel reduce of partials + mean/var + layernorm(512).

#define BB 16
#define TT 2048
#define DD 256
#define KK 8
#define ROWS 128
#define CH (TT / ROWS)
#define LOG2E 1.4426950408889634f
#define KREG 5                 // centers in registers; KK-KREG served from smem

__device__ float g_wx [BB * CH * KK * DD];
__device__ float g_wx2[BB * CH * KK * DD];
__device__ float g_sw [BB * CH * KK];

// ---- f32x2 packed math (sm_103a) ----
static __device__ __forceinline__ unsigned long long pk2(float lo, float hi) {
    unsigned long long r;
    asm("mov.b64 %0, {%1, %2};" : "=l"(r) : "f"(lo), "f"(hi));
    return r;
}
static __device__ __forceinline__ void upk2(unsigned long long v, float& a, float& b) {
    asm("mov.b64 {%0, %1}, %2;" : "=f"(a), "=f"(b) : "l"(v));
}
static __device__ __forceinline__ unsigned long long ffma2(unsigned long long a,
                                                           unsigned long long b,
                                                           unsigned long long c) {
    unsigned long long d;
    asm("fma.rn.f32x2 %0, %1, %2, %3;" : "=l"(d) : "l"(a), "l"(b), "l"(c));
    return d;
}
static __device__ __forceinline__ unsigned long long fmul2(unsigned long long a,
                                                           unsigned long long b) {
    unsigned long long d;
    asm("mul.rn.f32x2 %0, %1, %2;" : "=l"(d) : "l"(a), "l"(b));
    return d;
}
static __device__ __forceinline__ float ex2_fast(float v) {
    float r;
    asm("ex2.approx.f32 %0, %1;" : "=f"(r) : "f"(v));
    return r;
}

// 8-value reduce-scatter across 32 lanes. Every lane ends with the full warp
// sum of r[K_id], K_id = 4*bit4(lane) + 2*bit3(lane) + bit2(lane).
static __device__ __forceinline__ float rscat8(float r[8], bool b4, bool b8, bool b2) {
#pragma unroll
    for (int i = 0; i < 4; i++) {
        float sel = b4 ? r[i] : r[i + 4];
        float got = __shfl_xor_sync(0xffffffffu, sel, 16);
        r[i] = (b4 ? r[i + 4] : r[i]) + got;
    }
#pragma unroll
    for (int i = 0; i < 2; i++) {
        float sel = b8 ? r[i] : r[i + 2];
        float got = __shfl_xor_sync(0xffffffffu, sel, 8);
        r[i] = (b8 ? r[i + 2] : r[i]) + got;
    }
    {
        float sel = b2 ? r[0] : r[1];
        float got = __shfl_xor_sync(0xffffffffu, sel, 4);
        r[0] = (b2 ? r[1] : r[0]) + got;
    }
    r[0] += __shfl_xor_sync(0xffffffffu, r[0], 2);
    r[0] += __shfl_xor_sync(0xffffffffu, r[0], 1);
    return r[0];
}

// dots + reduce-scatter -> this lane's logit for its K_id
static __device__ __forceinline__ float compute_logit(
    const unsigned long long xp[4],
    const unsigned long long cc[KREG][4],
    const float (*sC)[DD],
    int lane, bool b4, bool b8, bool b2,
    float a2L, float ne2L)
{
    // smem-resident center rows first (hide LDS latency under the FMAs below)
    float4 sa[KK - KREG], sq[KK - KREG];
#pragma unroll
    for (int k = 0; k < KK - KREG; k++) {
        const float4* sc = (const float4*)sC[k];
        sa[k] = sc[lane];
        sq[k] = sc[32 + lane];
    }

    unsigned long long s2 = ffma2(xp[0], xp[0], ffma2(xp[1], xp[1],
                           ffma2(xp[2], xp[2], fmul2(xp[3], xp[3]))));
    float t0, t1; upk2(s2, t0, t1);
    const float x2 = t0 + t1;

    float r[KK];
#pragma unroll
    for (int k = 0; k < KREG; k++) {
        unsigned long long s = ffma2(xp[0], cc[k][0],
                               ffma2(xp[1], cc[k][1],
                               ffma2(xp[2], cc[k][2],
                               fmul2(xp[3], cc[k][3]))));
        float u, v; upk2(s, u, v);
        r[k] = fmaf(2.f, u + v, -x2);
    }
#pragma unroll
    for (int k = 0; k < KK - KREG; k++) {
        unsigned long long p0 = pk2(sa[k].x, sa[k].y), p1 = pk2(sa[k].z, sa[k].w);
        unsigned long long p2 = pk2(sq[k].x, sq[k].y), p3 = pk2(sq[k].z, sq[k].w);
        unsigned long long s = ffma2(xp[0], p0, ffma2(xp[1], p1,
                               ffma2(xp[2], p2, fmul2(xp[3], p3))));
        float u, v; upk2(s, u, v);
        r[KREG + k] = fmaf(2.f, u + v, -x2);
    }
    const float rv = rscat8(r, b4, b8, b2);
    return fmaf(a2L, rv, ne2L);
}

__global__ __launch_bounds__(128, 2)
void lde_main(const float* __restrict__ x,
              const float* __restrict__ centers,
              const float* __restrict__ scale,
              const float* __restrict__ temperature)
{
    const int tid  = threadIdx.x;
    const int warp = tid >> 5;
    const int lane = tid & 31;
    const int b    = blockIdx.x >> 4;
    const int ch   = blockIdx.x & 15;

    const bool b4 = (lane & 16) != 0;
    const bool b8 = (lane & 8) != 0;
    const bool b2 = (lane & 4) != 0;
    const int K_id = (b4 ? 4 : 0) + (b8 ? 2 : 0) + (b2 ? 1 : 0);

    __shared__ float sC  [KK - KREG][DD];
    __shared__ float sWX [KK][DD];
    __shared__ float sWX2[KK][DD];
    __shared__ float sSW [KK];

    // ---- prologue: centers ----
    unsigned long long cc[KREG][4];
    float c2p[KK];
    const float4* c4 = (const float4*)centers;
#pragma unroll
    for (int k = 0; k < KK; k++) {
        float4 a = __ldg(c4 + k * (DD / 4) + lane);
        float4 q = __ldg(c4 + k * (DD / 4) + 32 + lane);
        unsigned long long p0 = pk2(a.x, a.y), p1 = pk2(a.z, a.w);
        unsigned long long p2 = pk2(q.x, q.y), p3 = pk2(q.z, q.w);
        if (k < KREG) {
            cc[k][0] = p0; cc[k][1] = p1; cc[k][2] = p2; cc[k][3] = p3;
        } else if (warp == 0) {
            *(float4*)&sC[k - KREG][lane * 4]       = a;
            *(float4*)&sC[k - KREG][128 + lane * 4] = q;
        }
        unsigned long long s = ffma2(p0, p0, ffma2(p1, p1, ffma2(p2, p2, fmul2(p3, p3))));
        float u, v; upk2(s, u, v);
        c2p[k] = u + v;
    }
    const float c2L = rscat8(c2p, b4, b8, b2);

    const float tmp  = __ldg(temperature);
    const float a2L  = tmp * __ldg(scale + K_id) * LOG2E;
    const float ne2L = -a2L * c2L;
    __syncthreads();

    // accumulators
    unsigned long long aw[KK][4], aw2[KK][4];
    float asw = 0.f;
#pragma unroll
    for (int k = 0; k < KK; k++)
#pragma unroll
        for (int p = 0; p < 4; p++) { aw[k][p] = 0ull; aw2[k][p] = 0ull; }

    const int row0 = ch * ROWS + warp * (ROWS / 4);
    const float4* xb = (const float4*)(x + (size_t)b * TT * DD);
    const int NR = ROWS / 4;   // 32 rows per warp

    // ---- pipeline prologue: row 0 ----
    unsigned long long xpC[4];
    float logitC;
    {
        float4 a = __ldg(xb + (size_t)row0 * (DD / 4) + lane);
        float4 q = __ldg(xb + (size_t)row0 * (DD / 4) + 32 + lane);
        xpC[0] = pk2(a.x, a.y); xpC[1] = pk2(a.z, a.w);
        xpC[2] = pk2(q.x, q.y); xpC[3] = pk2(q.z, q.w);
    }
    float4 na = __ldg(xb + (size_t)(row0 + 1) * (DD / 4) + lane);
    float4 nb = __ldg(xb + (size_t)(row0 + 1) * (DD / 4) + 32 + lane);
    logitC = compute_logit(xpC, cc, sC, lane, b4, b8, b2, a2L, ne2L);

    // ---- pipelined body: softmax+accum(row i) || dots+rscat(row i+1) ----
#pragma unroll 1
    for (int i = 0; i < NR - 1; i++) {
        // softmax chain for row i (distributed over lane bits 2,3,4)
        float m = logitC;
        m = fmaxf(m, __shfl_xor_sync(0xffffffffu, m, 4));
        m = fmaxf(m, __shfl_xor_sync(0xffffffffu, m, 8));
        m = fmaxf(m, __shfl_xor_sync(0xffffffffu, m, 16));
        const float e = ex2_fast(logitC - m);
        float S = e;
        S += __shfl_xor_sync(0xffffffffu, S, 4);
        S += __shfl_xor_sync(0xffffffffu, S, 8);
        S += __shfl_xor_sync(0xffffffffu, S, 16);
        const float w = e * __fdividef(1.f, S);
        asw += w;

        // next row's data + dots (independent of the softmax chain above)
        unsigned long long xpN[4];
        xpN[0] = pk2(na.x, na.y); xpN[1] = pk2(na.z, na.w);
        xpN[2] = pk2(nb.x, nb.y); xpN[3] = pk2(nb.z, nb.w);
        {
            int nr = i + 2 < NR ? i + 2 : NR - 1;   // clamped prefetch, no branch
            const float4* nx = xb + (size_t)(row0 + nr) * (DD / 4);
            na = __ldg(nx + lane);
            nb = __ldg(nx + 32 + lane);
        }
        const float logitN = compute_logit(xpN, cc, sC, lane, b4, b8, b2, a2L, ne2L);

        // gather weights for row i (k at lane 4k)
        float wk[KK];
#pragma unroll
        for (int k = 0; k < KK; k++)
            wk[k] = __shfl_sync(0xffffffffu, w, k * 4);

        // accumulate row i: first-order, then square xpC in place for second-order
#pragma unroll
        for (int k = 0; k < KK; k++) {
            unsigned long long wp = pk2(wk[k], wk[k]);
            aw[k][0] = ffma2(wp, xpC[0], aw[k][0]);
            aw[k][1] = ffma2(wp, xpC[1], aw[k][1]);
            aw[k][2] = ffma2(wp, xpC[2], aw[k][2]);
            aw[k][3] = ffma2(wp, xpC[3], aw[k][3]);
        }
#pragma unroll
        for (int p = 0; p < 4; p++) xpC[p] = fmul2(xpC[p], xpC[p]);
#pragma unroll
        for (int k = 0; k < KK; k++) {
            unsigned long long wp = pk2(wk[k], wk[k]);
            aw2[k][0] = ffma2(wp, xpC[0], aw2[k][0]);
            aw2[k][1] = ffma2(wp, xpC[1], aw2[k][1]);
            aw2[k][2] = ffma2(wp, xpC[2], aw2[k][2]);
            aw2[k][3] = ffma2(wp, xpC[3], aw2[k][3]);
        }

        // rotate
        xpC[0] = xpN[0]; xpC[1] = xpN[1]; xpC[2] = xpN[2]; xpC[3] = xpN[3];
        logitC = logitN;
    }

    // ---- pipeline epilogue: softmax+accum for last row ----
    {
        float m = logitC;
        m = fmaxf(m, __shfl_xor_sync(0xffffffffu, m, 4));
        m = fmaxf(m, __shfl_xor_sync(0xffffffffu, m, 8));
        m = fmaxf(m, __shfl_xor_sync(0xffffffffu, m, 16));
        const float e = ex2_fast(logitC - m);
        float S = e;
        S += __shfl_xor_sync(0xffffffffu, S, 4);
        S += __shfl_xor_sync(0xffffffffu, S, 8);
        S += __shfl_xor_sync(0xffffffffu, S, 16);
        const float w = e * __fdividef(1.f, S);
        asw += w;

        float wk[KK];
#pragma unroll
        for (int k = 0; k < KK; k++)
            wk[k] = __shfl_sync(0xffffffffu, w, k * 4);
#pragma unroll
        for (int k = 0; k < KK; k++) {
            unsigned long long wp = pk2(wk[k], wk[k]);
            aw[k][0] = ffma2(wp, xpC[0], aw[k][0]);
            aw[k][1] = ffma2(wp, xpC[1], aw[k][1]);
            aw[k][2] = ffma2(wp, xpC[2], aw[k][2]);
            aw[k][3] = ffma2(wp, xpC[3], aw[k][3]);
        }
#pragma unroll
        for (int p = 0; p < 4; p++) xpC[p] = fmul2(xpC[p], xpC[p]);
#pragma unroll
        for (int k = 0; k < KK; k++) {
            unsigned long long wp = pk2(wk[k], wk[k]);
            aw2[k][0] = ffma2(wp, xpC[0], aw2[k][0]);
            aw2[k][1] = ffma2(wp, xpC[1], aw2[k][1]);
            aw2[k][2] = ffma2(wp, xpC[2], aw2[k][2]);
            aw2[k][3] = ffma2(wp, xpC[3], aw2[k][3]);
        }
    }

    // cross-warp merge (serialized, no atomics)
    for (int wv = 0; wv < 4; wv++) {
        if (warp == wv) {
#pragma unroll
            for (int k = 0; k < KK; k++) {
#pragma unroll
                for (int h = 0; h < 2; h++) {
                    float p0, p1, p2, p3;
                    upk2(aw[k][2 * h], p0, p1);
                    upk2(aw[k][2 * h + 1], p2, p3);
                    float* dst = &sWX[k][h * 128 + lane * 4];
                    if (wv == 0) { dst[0] = p0; dst[1] = p1; dst[2] = p2; dst[3] = p3; }
                    else         { dst[0] += p0; dst[1] += p1; dst[2] += p2; dst[3] += p3; }
                    upk2(aw2[k][2 * h], p0, p1);
                    upk2(aw2[k][2 * h + 1], p2, p3);
                    float* dst2 = &sWX2[k][h * 128 + lane * 4];
                    if (wv == 0) { dst2[0] = p0; dst2[1] = p1; dst2[2] = p2; dst2[3] = p3; }
                    else         { dst2[0] += p0; dst2[1] += p1; dst2[2] += p2; dst2[3] += p3; }
                }
            }
            if ((lane & 3) == 0) {
                int k = lane >> 2;
                if (wv == 0) sSW[k] = asw;
                else         sSW[k] += asw;
            }
        }
        __syncthreads();
    }

    // write partials (coalesced)
    const int cbase = (b * CH + ch) * KK;
    float4* gw  = (float4*)g_wx;
    float4* gw2 = (float4*)g_wx2;
    for (int idx = tid; idx < KK * DD / 4; idx += 128) {
        int k = idx >> 6;
        int q = idx & 63;
        *(gw  + (size_t)(cbase + k) * (DD / 4) + q) = *(const float4*)&sWX [k][q * 4];
        *(gw2 + (size_t)(cbase + k) * (DD / 4) + q) = *(const float4*)&sWX2[k][q * 4];
    }
    if (tid < KK) g_sw[cbase + tid] = sSW[tid];
}

// ---- K2: chunk-parallel reduce + mean/var + LN(512) ----
__global__ __launch_bounds__(512)
void lde_finalize(const float* __restrict__ centers, float* __restrict__ out)
{
    const int b = blockIdx.x >> 3;
    const int k = blockIdx.x & 7;
    const int tid = threadIdx.x;

    __shared__ float sWXc [CH][DD];
    __shared__ float sWX2c[CH][DD];
    __shared__ float sSum[2][DD];
    __shared__ float sStat[2 * DD];
    __shared__ float s16[CH];
    __shared__ float sSwTot;
    __shared__ float red[16];

    {
        const int c = tid >> 5;
        const int s = tid & 31;
        const size_t base = ((size_t)(b * CH + c) * KK + k) * (DD / 4);
        const float4* gw  = (const float4*)g_wx;
        const float4* gw2 = (const float4*)g_wx2;
        float4 v0 = __ldg(gw  + base + s);
        float4 v1 = __ldg(gw  + base + s + 32);
        float4 v2 = __ldg(gw2 + base + s);
        float4 v3 = __ldg(gw2 + base + s + 32);
        *(float4*)&sWXc [c][s * 4]       = v0;
        *(float4*)&sWXc [c][(s + 32) * 4] = v1;
        *(float4*)&sWX2c[c][s * 4]       = v2;
        *(float4*)&sWX2c[c][(s + 32) * 4] = v3;
        if (tid < CH) s16[tid] = g_sw[(b * CH + tid) * KK + k];
    }
    __syncthreads();

    {
        const int half = tid >> 8;
        const int d = tid & 255;
        float s = 0.f;
        if (half == 0) {
#pragma unroll
            for (int c = 0; c < CH; c++) s += sWXc[c][d];
        } else {
#pragma unroll
            for (int c = 0; c < CH; c++) s += sWX2c[c][d];
        }
        sSum[half][d] = s;
        if (tid == 0) {
            float t = 0.f;
#pragma unroll
            for (int c = 0; c < CH; c++) t += s16[c];
            sSwTot = t;
        }
    }
    __syncthreads();

    if (tid < DD) {
        const float sw   = sSwTot;
        const float swx  = sSum[0][tid];
        const float swx2 = sSum[1][tid];
        const float cv   = __ldg(centers + k * DD + tid);
        const float mean = fmaf(-cv, sw, swx);
        const float E    = fmaf(cv * cv, sw, fmaf(-2.f * cv, swx, swx2));
        const float var  = fmaf(-mean, mean, E);
        sStat[tid]      = mean;
        sStat[DD + tid] = var;
    }
    __syncthreads();

    const float v0 = sStat[tid];
    float s = v0;
#pragma unroll
    for (int off = 16; off; off >>= 1) s += __shfl_xor_sync(0xffffffffu, s, off);
    if ((tid & 31) == 0) red[tid >> 5] = s;
    __syncthreads();
    float tot = 0.f;
#pragma unroll
    for (int i = 0; i < 16; i++) tot += red[i];
    const float mu = tot * (1.f / 512.f);
    __syncthreads();

    const float dm = v0 - mu;
    float sq = dm * dm;
#pragma unroll
    for (int off = 16; off; off >>= 1) sq += __shfl_xor_sync(0xffffffffu, sq, off);
    if ((tid & 31) == 0) red[tid >> 5] = sq;
    __syncthreads();
    float tot2 = 0.f;
#pragma unroll
    for (int i = 0; i < 16; i++) tot2 += red[i];
    const float rstd = rsqrtf(tot2 * (1.f / 512.f) + 1e-5f);

    out[(size_t)b * (KK * 2 * DD) + k * (2 * DD) + tid] = dm * rstd;
}

extern "C" void kernel_launch(void* const* d_in, const int* in_sizes, int n_in,
                              void* d_out, int out_size)
{
    const float* x = nullptr; const float* centers = nullptr;
    const float* scale = nullptr; const float* temperature = nullptr;
    for (int i = 0; i < n_in; i++) {
        switch (in_sizes[i]) {
            case BB * TT * DD: x = (const float*)d_in[i]; break;
            case KK * DD:      centers = (const float*)d_in[i]; break;
            case KK:           scale = (const float*)d_in[i]; break;
            case 1:            temperature = (const float*)d_in[i]; break;
        }
    }
    lde_main<<<BB * CH, 128>>>(x, centers, scale, temperature);
    lde_finalize<<<BB * KK, 512>>>(centers, (float*)d_out);
}

// round 5
// speedup vs baseline: 1.5944x; 1.1786x over previous
#include <cuda_runtime.h>
#include <cstdint>

// EnhancedLDEPooling: B=16, T=2048, D=256, K=8
// K1: 256-thread blocks, cp.async-staged 16-row tiles, warp handles 2 rows/tile.
//     Batched reduce-scatter (16 values over 32 lanes), softmax shared by 2 rows,
//     weight broadcast via smem. Log-tree cross-warp merge.
// K2: chunk reduce (CH=8) + mean/var + LN(512).

#define BB 16
#define TT 2048
#define DD 256
#define KK 8
#define ROWS 256              // rows per block (256 threads)
#define CH (TT / ROWS)        // 8 chunks per batch
#define NTILE 16              // tiles of 16 rows per block
#define LOG2E 1.4426950408889634f
#define KREG 5                // centers in registers; rest from smem

__device__ float g_wx [BB * CH * KK * DD];   // 1 MB
__device__ float g_wx2[BB * CH * KK * DD];   // 1 MB
__device__ float g_sw [BB * CH * KK];

typedef unsigned long long u64;

// ---- f32x2 packed math ----
static __device__ __forceinline__ u64 pk2(float lo, float hi) {
    u64 r; asm("mov.b64 %0, {%1, %2};" : "=l"(r) : "f"(lo), "f"(hi)); return r;
}
static __device__ __forceinline__ void upk2(u64 v, float& a, float& b) {
    asm("mov.b64 {%0, %1}, %2;" : "=f"(a), "=f"(b) : "l"(v));
}
static __device__ __forceinline__ u64 ffma2(u64 a, u64 b, u64 c) {
    u64 d; asm("fma.rn.f32x2 %0, %1, %2, %3;" : "=l"(d) : "l"(a), "l"(b), "l"(c)); return d;
}
static __device__ __forceinline__ u64 fmul2(u64 a, u64 b) {
    u64 d; asm("mul.rn.f32x2 %0, %1, %2;" : "=l"(d) : "l"(a), "l"(b)); return d;
}
static __device__ __forceinline__ u64 fadd2(u64 a, u64 b) {
    u64 d; asm("add.rn.f32x2 %0, %1, %2;" : "=l"(d) : "l"(a), "l"(b)); return d;
}
static __device__ __forceinline__ float ex2_fast(float v) {
    float r; asm("ex2.approx.f32 %0, %1;" : "=f"(r) : "f"(v)); return r;
}
static __device__ __forceinline__ uint32_t smem_u32(const void* p) {
    return (uint32_t)__cvta_generic_to_shared(p);
}
static __device__ __forceinline__ void cp16(uint32_t dst, const void* src) {
    asm volatile("cp.async.cg.shared.global [%0], [%1], 16;" :: "r"(dst), "l"(src));
}
static __device__ __forceinline__ void cp_commit() {
    asm volatile("cp.async.commit_group;");
}
static __device__ __forceinline__ void cp_wait1() {
    asm volatile("cp.async.wait_group 1;");
}

// prologue-only: 8-value reduce-scatter (k = lane>>2)
static __device__ __forceinline__ float rscat8(float r[8], int lane) {
    const bool t4 = (lane & 16) != 0, t3 = (lane & 8) != 0, t2 = (lane & 4) != 0;
#pragma unroll
    for (int i = 0; i < 4; i++) {
        float sel  = t4 ? r[i] : r[i + 4];
        float keep = t4 ? r[i + 4] : r[i];
        r[i] = keep + __shfl_xor_sync(0xffffffffu, sel, 16);
    }
#pragma unroll
    for (int i = 0; i < 2; i++) {
        float sel  = t3 ? r[i] : r[i + 2];
        float keep = t3 ? r[i + 2] : r[i];
        r[i] = keep + __shfl_xor_sync(0xffffffffu, sel, 8);
    }
    {
        float sel  = t2 ? r[0] : r[1];
        float keep = t2 ? r[1] : r[0];
        r[0] = keep + __shfl_xor_sync(0xffffffffu, sel, 4);
    }
    r[0] += __shfl_xor_sync(0xffffffffu, r[0], 2);
    r[0] += __shfl_xor_sync(0xffffffffu, r[0], 1);
    return r[0];
}

// 16-value (2 rows x 8 k) reduce-scatter: lane ends with full warp sum of
// v[r*8+k] with k = lane>>2, r = (lane>>1)&1 (copies on bit0).
static __device__ __forceinline__ float rscat16(const float v[16], int lane) {
    const bool t4 = (lane & 16) != 0, t3 = (lane & 8) != 0;
    const bool t2 = (lane & 4) != 0,  t1 = (lane & 2) != 0;
    float u[8];
#pragma unroll
    for (int r = 0; r < 2; r++)
#pragma unroll
        for (int i = 0; i < 4; i++) {
            float sel  = t4 ? v[r * 8 + i] : v[r * 8 + i + 4];
            float keep = t4 ? v[r * 8 + i + 4] : v[r * 8 + i];
            u[r * 4 + i] = keep + __shfl_xor_sync(0xffffffffu, sel, 16);
        }
    float w2[4];
#pragma unroll
    for (int r = 0; r < 2; r++)
#pragma unroll
        for (int i = 0; i < 2; i++) {
            float sel  = t3 ? u[r * 4 + i] : u[r * 4 + i + 2];
            float keep = t3 ? u[r * 4 + i + 2] : u[r * 4 + i];
            w2[r * 2 + i] = keep + __shfl_xor_sync(0xffffffffu, sel, 8);
        }
    float y[2];
#pragma unroll
    for (int r = 0; r < 2; r++) {
        float sel  = t2 ? w2[r * 2] : w2[r * 2 + 1];
        float keep = t2 ? w2[r * 2 + 1] : w2[r * 2];
        y[r] = keep + __shfl_xor_sync(0xffffffffu, sel, 4);
    }
    float sel  = t1 ? y[0] : y[1];
    float keep = t1 ? y[1] : y[0];
    float z = keep + __shfl_xor_sync(0xffffffffu, sel, 2);
    z += __shfl_xor_sync(0xffffffffu, z, 1);
    return z;
}

__global__ __launch_bounds__(256, 1)
void lde_main(const float* __restrict__ x,
              const float* __restrict__ centers,
              const float* __restrict__ scale,
              const float* __restrict__ temperature)
{
    const int tid  = threadIdx.x;
    const int warp = tid >> 5;
    const int lane = tid & 31;
    const int b    = blockIdx.x >> 3;
    const int ch   = blockIdx.x & 7;
    const int K_id = lane >> 2;

    __shared__ float sX[2][NTILE * DD];        // 32 KB staging (reused for merge)
    __shared__ float sC[KK - KREG][DD];        // 3 KB
    __shared__ float sWtab[8][16];             // per-warp weight table
    __shared__ float sSWb[8][KK];

    // ---- prologue: centers ----
    u64 cc[KREG][4];
    float c2p[KK];
    const float4* c4 = (const float4*)centers;
#pragma unroll
    for (int k = 0; k < KK; k++) {
        float4 a = __ldg(c4 + k * (DD / 4) + lane);
        float4 q = __ldg(c4 + k * (DD / 4) + 32 + lane);
        u64 p0 = pk2(a.x, a.y), p1 = pk2(a.z, a.w);
        u64 p2 = pk2(q.x, q.y), p3 = pk2(q.z, q.w);
        if (k < KREG) {
            cc[k][0] = p0; cc[k][1] = p1; cc[k][2] = p2; cc[k][3] = p3;
        } else if (warp == 0) {
            *(float4*)&sC[k - KREG][lane * 4]       = a;
            *(float4*)&sC[k - KREG][128 + lane * 4] = q;
        }
        u64 s = ffma2(p0, p0, ffma2(p1, p1, ffma2(p2, p2, fmul2(p3, p3))));
        float u, v; upk2(s, u, v);
        c2p[k] = u + v;
    }
    const float c2L  = rscat8(c2p, lane);
    const float tmp  = __ldg(temperature);
    const float a2L  = tmp * __ldg(scale + K_id) * LOG2E;
    const float ne2L = -a2L * c2L;

    // accumulators: lane owns dims {4l..4l+3} and {128+4l..128+4l+3}, all k
    u64 aw[KK][4], aw2[KK][4];
    float asw = 0.f;
#pragma unroll
    for (int k = 0; k < KK; k++)
#pragma unroll
        for (int p = 0; p < 4; p++) { aw[k][p] = 0ull; aw2[k][p] = 0ull; }

    const float4* xb4 = (const float4*)(x + (size_t)b * TT * DD) +
                        (size_t)(ch * ROWS) * (DD / 4);

    // issue tile tt (clamped) into buffer bf: 4 cp.async.128 per thread
    auto issue_tile = [&](int tt, int bf) {
        tt = tt < NTILE ? tt : NTILE - 1;
        const float4* src = xb4 + (size_t)tt * 16 * (DD / 4);
        uint32_t dst = smem_u32(&sX[bf][0]);
#pragma unroll
        for (int j = 0; j < 4; j++) {
            int idx = j * 256 + tid;
            cp16(dst + idx * 16, src + idx);
        }
        cp_commit();
    };

    issue_tile(0, 0);
    cp_commit();   // harmless extra empty group boundary safety

#pragma unroll 1
    for (int t = 0; t < NTILE; t++) {
        issue_tile(t + 1, (t + 1) & 1);
        cp_wait1();
        __syncthreads();

        const float* tb = &sX[t & 1][0];
        const float4* row0 = (const float4*)(tb + (2 * warp) * DD);
        const float4* row1 = (const float4*)(tb + (2 * warp + 1) * DD);

        // phase 1: load 2 rows (lane's 8 dims each), dot partials
        u64 xr[2][4];
        {
            float4 a = row0[lane], q = row0[32 + lane];
            xr[0][0] = pk2(a.x, a.y); xr[0][1] = pk2(a.z, a.w);
            xr[0][2] = pk2(q.x, q.y); xr[0][3] = pk2(q.z, q.w);
            float4 a1 = row1[lane], q1 = row1[32 + lane];
            xr[1][0] = pk2(a1.x, a1.y); xr[1][1] = pk2(a1.z, a1.w);
            xr[1][2] = pk2(q1.x, q1.y); xr[1][3] = pk2(q1.z, q1.w);
        }

        float v[16];
#pragma unroll
        for (int r = 0; r < 2; r++) {
            u64 s2 = ffma2(xr[r][0], xr[r][0], ffma2(xr[r][1], xr[r][1],
                     ffma2(xr[r][2], xr[r][2], fmul2(xr[r][3], xr[r][3]))));
            float t0, t1; upk2(s2, t0, t1);
            const float x2 = t0 + t1;
#pragma unroll
            for (int k = 0; k < KREG; k++) {
                u64 s = ffma2(xr[r][0], cc[k][0], ffma2(xr[r][1], cc[k][1],
                        ffma2(xr[r][2], cc[k][2], fmul2(xr[r][3], cc[k][3]))));
                float u, w; upk2(s, u, w);
                v[r * 8 + k] = fmaf(2.f, u + w, -x2);
            }
#pragma unroll
            for (int k = KREG; k < KK; k++) {
                const float4* sc = (const float4*)sC[k - KREG];
                float4 a = sc[lane], q = sc[32 + lane];
                u64 p0 = pk2(a.x, a.y), p1 = pk2(a.z, a.w);
                u64 p2 = pk2(q.x, q.y), p3 = pk2(q.z, q.w);
                u64 s = ffma2(xr[r][0], p0, ffma2(xr[r][1], p1,
                        ffma2(xr[r][2], p2, fmul2(xr[r][3], p3))));
                float u, w; upk2(s, u, w);
                v[r * 8 + k] = fmaf(2.f, u + w, -x2);
            }
        }

        // batched reduce-scatter + softmax (serves both rows)
        const float rv    = rscat16(v, lane);
        const float logit = fmaf(a2L, rv, ne2L);
        float m = logit;
        m = fmaxf(m, __shfl_xor_sync(0xffffffffu, m, 4));
        m = fmaxf(m, __shfl_xor_sync(0xffffffffu, m, 8));
        m = fmaxf(m, __shfl_xor_sync(0xffffffffu, m, 16));
        const float e = ex2_fast(logit - m);
        float S = e;
        S += __shfl_xor_sync(0xffffffffu, S, 4);
        S += __shfl_xor_sync(0xffffffffu, S, 8);
        S += __shfl_xor_sync(0xffffffffu, S, 16);
        const float w = e * __fdividef(1.f, S);
        if ((lane & 1) == 0) {
            asw += w;
            sWtab[warp][((lane >> 1) & 1) * 8 + K_id] = w;
        }
        __syncwarp();

        // phase 2: accumulate both rows (weights via smem broadcast)
        const float4* tab = (const float4*)sWtab[warp];
#pragma unroll
        for (int r = 0; r < 2; r++) {
            float4 wlo = tab[r * 2], whi = tab[r * 2 + 1];
            float wk[KK] = {wlo.x, wlo.y, wlo.z, wlo.w, whi.x, whi.y, whi.z, whi.w};
#pragma unroll
            for (int k = 0; k < KK; k++) {
                u64 wp = pk2(wk[k], wk[k]);
                aw[k][0] = ffma2(wp, xr[r][0], aw[k][0]);
                aw[k][1] = ffma2(wp, xr[r][1], aw[k][1]);
                aw[k][2] = ffma2(wp, xr[r][2], aw[k][2]);
                aw[k][3] = ffma2(wp, xr[r][3], aw[k][3]);
            }
#pragma unroll
            for (int p = 0; p < 4; p++) xr[r][p] = fmul2(xr[r][p], xr[r][p]);
#pragma unroll
            for (int k = 0; k < KK; k++) {
                u64 wp = pk2(wk[k], wk[k]);
                aw2[k][0] = ffma2(wp, xr[r][0], aw2[k][0]);
                aw2[k][1] = ffma2(wp, xr[r][1], aw2[k][1]);
                aw2[k][2] = ffma2(wp, xr[r][2], aw2[k][2]);
                aw2[k][3] = ffma2(wp, xr[r][3], aw2[k][3]);
            }
        }
        __syncthreads();   // everyone done with this buffer before it is re-filled
    }

    // per-warp sw reduce (k spread over lane bits 2-4; copies on bits 0-1 hold 0)
    asw += __shfl_xor_sync(0xffffffffu, asw, 1);
    asw += __shfl_xor_sync(0xffffffffu, asw, 2);
    if ((lane & 3) == 0) sSWb[warp][K_id] = asw;

    // ---- log-tree cross-warp merge in reused staging smem ----
    u64* aw_f  = &aw[0][0];
    u64* aw2_f = &aw2[0][0];
    u64* mb = (u64*)&sX[0][0];     // 4096 u64 slots (32 KB)
    __syncthreads();

    // level 1 (8 -> 4): aw, then aw2
    if (warp >= 4) {
#pragma unroll
        for (int j = 0; j < 32; j++) mb[(warp - 4) * 1024 + j * 32 + lane] = aw_f[j];
    }
    __syncthreads();
    if (warp < 4) {
#pragma unroll
        for (int j = 0; j < 32; j++)
            aw_f[j] = fadd2(aw_f[j], mb[warp * 1024 + j * 32 + lane]);
    }
    __syncthreads();
    if (warp >= 4) {
#pragma unroll
        for (int j = 0; j < 32; j++) mb[(warp - 4) * 1024 + j * 32 + lane] = aw2_f[j];
    }
    __syncthreads();
    if (warp < 4) {
#pragma unroll
        for (int j = 0; j < 32; j++)
            aw2_f[j] = fadd2(aw2_f[j], mb[warp * 1024 + j * 32 + lane]);
    }
    __syncthreads();

    // level 2 (4 -> 2): both arrays at once
    if (warp == 2 || warp == 3) {
        int base = (warp - 2) * 2048;
#pragma unroll
        for (int j = 0; j < 32; j++) {
            mb[base + j * 32 + lane]        = aw_f[j];
            mb[base + 1024 + j * 32 + lane] = aw2_f[j];
        }
    }
    __syncthreads();
    if (warp < 2) {
        int base = warp * 2048;
#pragma unroll
        for (int j = 0; j < 32; j++) {
            aw_f[j]  = fadd2(aw_f[j],  mb[base + j * 32 + lane]);
            aw2_f[j] = fadd2(aw2_f[j], mb[base + 1024 + j * 32 + lane]);
        }
    }
    __syncthreads();

    // level 3 (2 -> 1)
    if (warp == 1) {
#pragma unroll
        for (int j = 0; j < 32; j++) {
            mb[j * 32 + lane]        = aw_f[j];
            mb[1024 + j * 32 + lane] = aw2_f[j];
        }
    }
    __syncthreads();
    if (warp == 0) {
#pragma unroll
        for (int j = 0; j < 32; j++) {
            aw_f[j]  = fadd2(aw_f[j],  mb[j * 32 + lane]);
            aw2_f[j] = fadd2(aw2_f[j], mb[1024 + j * 32 + lane]);
        }
        // write scratch directly
        const int cbase = (b * CH + ch) * KK;
        float4* gw  = (float4*)g_wx;
        float4* gw2 = (float4*)g_wx2;
#pragma unroll
        for (int k = 0; k < KK; k++) {
            float4 f;
            upk2(aw[k][0], f.x, f.y); upk2(aw[k][1], f.z, f.w);
            gw[(size_t)(cbase + k) * 64 + lane] = f;
            upk2(aw[k][2], f.x, f.y); upk2(aw[k][3], f.z, f.w);
            gw[(size_t)(cbase + k) * 64 + 32 + lane] = f;
            upk2(aw2[k][0], f.x, f.y); upk2(aw2[k][1], f.z, f.w);
            gw2[(size_t)(cbase + k) * 64 + lane] = f;
            upk2(aw2[k][2], f.x, f.y); upk2(aw2[k][3], f.z, f.w);
            gw2[(size_t)(cbase + k) * 64 + 32 + lane] = f;
        }
    }
    if (tid < KK) {
        float s = 0.f;
#pragma unroll
        for (int wv = 0; wv < 8; wv++) s += sSWb[wv][tid];
        g_sw[(b * CH + ch) * KK + tid] = s;
    }
}

// ---- K2: chunk reduce (CH=8) + mean/var + LN(512) ----
__global__ __launch_bounds__(512)
void lde_finalize(const float* __restrict__ centers, float* __restrict__ out)
{
    const int b = blockIdx.x >> 3;
    const int k = blockIdx.x & 7;
    const int tid = threadIdx.x;

    __shared__ float sA[CH][DD];     // 8 KB
    __shared__ float sB[CH][DD];     // 8 KB
    __shared__ float sSum[2 * DD];
    __shared__ float sStat[2 * DD];
    __shared__ float sSwTot;
    __shared__ float red[16];

    {
        const int c = tid >> 6;          // 0..7
        const int g = tid & 63;          // float4 index
        const size_t base = ((size_t)(b * CH + c) * KK + k) * (DD / 4) + g;
        *(float4*)&sA[c][g * 4] = __ldg((const float4*)g_wx  + base);
        *(float4*)&sB[c][g * 4] = __ldg((const float4*)g_wx2 + base);
        if (tid == 0) {
            float s = 0.f;
#pragma unroll
            for (int c2 = 0; c2 < CH; c2++) s += g_sw[(b * CH + c2) * KK + k];
            sSwTot = s;
        }
    }
    __syncthreads();

    {
        const int half = tid >> 8;
        const int d = tid & 255;
        float s = 0.f;
        if (half == 0) {
#pragma unroll
            for (int c = 0; c < CH; c++) s += sA[c][d];
        } else {
#pragma unroll
            for (int c = 0; c < CH; c++) s += sB[c][d];
        }
        sSum[half * DD + d] = s;
    }
    __syncthreads();

    if (tid < DD) {
        const float sw   = sSwTot;
        const float swx  = sSum[tid];
        const float swx2 = sSum[DD + tid];
        const float cv   = __ldg(centers + k * DD + tid);
        const float mean = fmaf(-cv, sw, swx);
        const float E    = fmaf(cv * cv, sw, fmaf(-2.f * cv, swx, swx2));
        const float var  = fmaf(-mean, mean, E);
        sStat[tid]      = mean;
        sStat[DD + tid] = var;
    }
    __syncthreads();

    const float v0 = sStat[tid];
    float s = v0;
#pragma unroll
    for (int off = 16; off; off >>= 1) s += __shfl_xor_sync(0xffffffffu, s, off);
    if ((tid & 31) == 0) red[tid >> 5] = s;
    __syncthreads();
    float tot = 0.f;
#pragma unroll
    for (int i = 0; i < 16; i++) tot += red[i];
    const float mu = tot * (1.f / 512.f);
    __syncthreads();

    const float dm = v0 - mu;
    float sq = dm * dm;
#pragma unroll
    for (int off = 16; off; off >>= 1) sq += __shfl_xor_sync(0xffffffffu, sq, off);
    if ((tid & 31) == 0) red[tid >> 5] = sq;
    __syncthreads();
    float tot2 = 0.f;
#pragma unroll
    for (int i = 0; i < 16; i++) tot2 += red[i];
    const float rstd = rsqrtf(tot2 * (1.f / 512.f) + 1e-5f);

    out[(size_t)b * (KK * 2 * DD) + k * (2 * DD) + tid] = dm * rstd;
}

extern "C" void kernel_launch(void* const* d_in, const int* in_sizes, int n_in,
                              void* d_out, int out_size)
{
    const float* x = nullptr; const float* centers = nullptr;
    const float* scale = nullptr; const float* temperature = nullptr;
    for (int i = 0; i < n_in; i++) {
        switch (in_sizes[i]) {
            case BB * TT * DD: x = (const float*)d_in[i]; break;
            case KK * DD:      centers = (const float*)d_in[i]; break;
            case KK:           scale = (const float*)d_in[i]; break;
            case 1:            temperature = (const float*)d_in[i]; break;
        }
    }
    lde_main<<<BB * CH, 256>>>(x, centers, scale, temperature);
    lde_finalize<<<BB * KK, 512>>>(centers, (float*)d_out);
}